// round 6
// baseline (speedup 1.0000x reference)
#include <cuda_runtime.h>

#define BATCH 8
#define DIM 256
#define SEQ 16384
#define KK 3
#define HID 85
#define OUTC (DIM*KK)
#define BN_EPS 1e-5f
#define FULLM 0xffffffffu

#define BCHUNK 4            // batches per chunk (67 MB of x, fits in 126 MB L2)

// Scratch (device globals — no allocation allowed)
__device__ float g_pooled[BATCH * DIM];
__device__ float g_w[BATCH * OUTC];

// ---------------------------------------------------------------------------
// Kernel 1: mean over seq. grid=(DIM, BCHUNK), block=512, 8 front-batched f4.
// ---------------------------------------------------------------------------
__global__ void pool_kernel(const float* __restrict__ x, int b0) {
    const int c = blockIdx.x;
    const int b = b0 + blockIdx.y;
    const size_t rowoff = ((size_t)b * DIM + c) * SEQ;
    const float4* row = (const float4*)(x + rowoff);

    float4 v[8];
    #pragma unroll
    for (int j = 0; j < 8; j++)
        v[j] = row[threadIdx.x + j * 512];

    float s = 0.f;
    #pragma unroll
    for (int j = 0; j < 8; j++)
        s += (v[j].x + v[j].y) + (v[j].z + v[j].w);

    #pragma unroll
    for (int off = 16; off > 0; off >>= 1)
        s += __shfl_down_sync(FULLM, s, off);

    __shared__ float sm[16];
    if ((threadIdx.x & 31) == 0) sm[threadIdx.x >> 5] = s;
    __syncthreads();
    if (threadIdx.x < 16) {
        float t = sm[threadIdx.x];
        #pragma unroll
        for (int off = 8; off > 0; off >>= 1)
            t += __shfl_down_sync(0xffffu, t, off);
        if (threadIdx.x == 0) g_pooled[b * DIM + c] = t * (1.f / SEQ);
    }
}

// ---------------------------------------------------------------------------
// Kernel 2: tiny MLP. grid=(4, BCHUNK), block=256.
// ---------------------------------------------------------------------------
__global__ void mlp_kernel(const float* __restrict__ w1,
                           const float* __restrict__ gamma,
                           const float* __restrict__ beta,
                           const float* __restrict__ mean,
                           const float* __restrict__ var,
                           const float* __restrict__ w2,
                           const float* __restrict__ b2, int b0) {
    const int b = b0 + blockIdx.y;
    const int chunk = blockIdx.x;          // 0..3, 192 outputs each
    const int tid = threadIdx.x;

    __shared__ float ps[DIM];
    __shared__ float ys[HID];

    ps[tid] = g_pooled[b * DIM + tid];
    __syncthreads();

    if (tid < HID) {
        const float* wr = w1 + tid * DIM;
        float acc = 0.f;
        #pragma unroll 8
        for (int c = 0; c < DIM; c++) acc = fmaf(wr[c], ps[c], acc);
        float v = (acc - mean[tid]) * (gamma[tid] * rsqrtf(var[tid] + BN_EPS)) + beta[tid];
        ys[tid] = fmaxf(v, 0.f);
    }
    __syncthreads();

    const int o = chunk * 192 + tid;
    if (tid < 192) {
        const float* wr = w2 + o * HID;
        float acc = b2[o];
        #pragma unroll 5
        for (int h = 0; h < HID; h++) acc = fmaf(wr[h], ys[h], acc);
        g_w[b * OUTC + o] = acc;
    }
}

// ---------------------------------------------------------------------------
// Kernel 3: depthwise 3-tap conv, pad=1, + bias. grid=(8, DIM, BCHUNK),
// block=256, 2 float4s/thread. Halo via warp shuffle. SAME traversal order
// as pool (consume oldest L2-resident x lines first). __stcs stores so the
// output stream recycles its own evict-first lines instead of evicting x.
// ---------------------------------------------------------------------------
__global__ void conv_kernel(const float* __restrict__ x,
                            const float* __restrict__ bias,
                            float* __restrict__ out, int b0) {
    const int b = b0 + blockIdx.z;
    const int c = blockIdx.y;
    const int chunk = blockIdx.x;                    // 0..7
    const int tid = threadIdx.x;
    const int lane = tid & 31;
    const size_t rowoff = ((size_t)b * DIM + c) * SEQ;

    const float w0  = g_w[b * OUTC + c * KK + 0];
    const float w1v = g_w[b * OUTC + c * KK + 1];
    const float w2v = g_w[b * OUTC + c * KK + 2];
    const float bb  = __ldg(bias + c);

    const int p0 = chunk * 256 + tid;          // float4 idx, first half
    const int p1 = p0 + 2048;                  // second half
    const int t0 = p0 * 4;
    const int t1 = p1 * 4;

    const float4 xa = *(const float4*)(x + rowoff + t0);
    const float4 xb = *(const float4*)(x + rowoff + t1);

    float xla = __shfl_up_sync(FULLM, xa.w, 1);
    float xra = __shfl_down_sync(FULLM, xa.x, 1);
    float xlb = __shfl_up_sync(FULLM, xb.w, 1);
    float xrb = __shfl_down_sync(FULLM, xb.x, 1);

    if (lane == 0) {
        xla = (t0 == 0) ? 0.f : __ldg(x + rowoff + t0 - 1);
        xlb = __ldg(x + rowoff + t1 - 1);
    }
    if (lane == 31) {
        xra = __ldg(x + rowoff + t0 + 4);
        xrb = (t1 + 4 >= SEQ) ? 0.f : __ldg(x + rowoff + t1 + 4);
    }

    float4 oa, ob;
    oa.x = fmaf(w0, xla,  fmaf(w1v, xa.x, fmaf(w2v, xa.y, bb)));
    oa.y = fmaf(w0, xa.x, fmaf(w1v, xa.y, fmaf(w2v, xa.z, bb)));
    oa.z = fmaf(w0, xa.y, fmaf(w1v, xa.z, fmaf(w2v, xa.w, bb)));
    oa.w = fmaf(w0, xa.z, fmaf(w1v, xa.w, fmaf(w2v, xra,  bb)));

    ob.x = fmaf(w0, xlb,  fmaf(w1v, xb.x, fmaf(w2v, xb.y, bb)));
    ob.y = fmaf(w0, xb.x, fmaf(w1v, xb.y, fmaf(w2v, xb.z, bb)));
    ob.z = fmaf(w0, xb.y, fmaf(w1v, xb.z, fmaf(w2v, xb.w, bb)));
    ob.w = fmaf(w0, xb.z, fmaf(w1v, xb.w, fmaf(w2v, xrb,  bb)));

    __stcs((float4*)(out + rowoff + t0), oa);
    __stcs((float4*)(out + rowoff + t1), ob);
}

// ---------------------------------------------------------------------------
// Launch: 2 chunks of 4 batches. Within a chunk the x working set (67 MB)
// stays L2-resident between pool and conv.
// Inputs: x, w1, bn_gamma, bn_beta, bn_mean, bn_var, w2, b2, bias.
// ---------------------------------------------------------------------------
extern "C" void kernel_launch(void* const* d_in, const int* in_sizes, int n_in,
                              void* d_out, int out_size) {
    const float* x     = (const float*)d_in[0];
    const float* w1    = (const float*)d_in[1];
    const float* gamma = (const float*)d_in[2];
    const float* beta  = (const float*)d_in[3];
    const float* mean  = (const float*)d_in[4];
    const float* var   = (const float*)d_in[5];
    const float* w2    = (const float*)d_in[6];
    const float* b2    = (const float*)d_in[7];
    const float* bias  = (const float*)d_in[8];
    float* out = (float*)d_out;

    dim3 pg(DIM, BCHUNK);
    dim3 mg(4, BCHUNK);
    dim3 cg(8, DIM, BCHUNK);

    for (int b0 = 0; b0 < BATCH; b0 += BCHUNK) {
        pool_kernel<<<pg, 512>>>(x, b0);
        mlp_kernel<<<mg, 256>>>(w1, gamma, beta, mean, var, w2, b2, b0);
        conv_kernel<<<cg, 256>>>(x, bias, out, b0);
    }
}

// round 7
// speedup vs baseline: 1.2800x; 1.2800x over previous
#include <cuda_runtime.h>

#define BATCH 8
#define DIM 256
#define SEQ 16384
#define KK 3
#define HID 85
#define OUTC (DIM*KK)
#define BN_EPS 1e-5f
#define FULLM 0xffffffffu

// Scratch (device globals — no allocation allowed)
__device__ float g_pooled[BATCH * DIM];
__device__ float g_w[BATCH * OUTC];
__device__ unsigned g_count[BATCH];   // zero-initialized; reset by finisher => replay-safe

// ---------------------------------------------------------------------------
// Kernel 1: pool + fused MLP tail.
// grid=(DIM, BATCH), block=512. Each block mean-pools one (b,c) row.
// The LAST block to finish batch b (per-batch atomic counter) computes
// y[85] = ReLU(BN(w1 @ pooled[b])) and w[768] = w2 @ y + b2 for that batch,
// overlapping with other batches' pool blocks. No separate mlp kernel.
// ---------------------------------------------------------------------------
__global__ void pool_mlp_kernel(const float* __restrict__ x,
                                const float* __restrict__ w1,
                                const float* __restrict__ gamma,
                                const float* __restrict__ beta,
                                const float* __restrict__ mean,
                                const float* __restrict__ var,
                                const float* __restrict__ w2,
                                const float* __restrict__ b2) {
    const int c = blockIdx.x;
    const int b = blockIdx.y;
    const int tid = threadIdx.x;
    const size_t rowoff = ((size_t)b * DIM + c) * SEQ;
    const float4* row = (const float4*)(x + rowoff);

    // ---- mean over the row: 8 front-batched float4 loads ----
    float4 v[8];
    #pragma unroll
    for (int j = 0; j < 8; j++)
        v[j] = row[tid + j * 512];

    float s = 0.f;
    #pragma unroll
    for (int j = 0; j < 8; j++)
        s += (v[j].x + v[j].y) + (v[j].z + v[j].w);

    #pragma unroll
    for (int off = 16; off > 0; off >>= 1)
        s += __shfl_down_sync(FULLM, s, off);

    __shared__ float sm[16];
    __shared__ int is_last_s;
    if ((tid & 31) == 0) sm[tid >> 5] = s;
    __syncthreads();
    if (tid < 16) {
        float t = sm[tid];
        #pragma unroll
        for (int off = 8; off > 0; off >>= 1)
            t += __shfl_down_sync(0xffffu, t, off);
        if (tid == 0) {
            g_pooled[b * DIM + c] = t * (1.f / SEQ);
            __threadfence();                              // release pooled value
            unsigned r = atomicAdd(&g_count[b], 1u);
            is_last_s = (r == DIM - 1);
        }
    }
    __syncthreads();
    if (!is_last_s) return;

    // ---- last block for batch b: run the MLP for this batch ----
    __threadfence();                                      // acquire all pooled[b]
    __shared__ float ps[DIM];
    __shared__ float ys[HID];

    if (tid < DIM) ps[tid] = __ldcg(g_pooled + b * DIM + tid);
    __syncthreads();

    if (tid < HID) {
        const float* wr = w1 + tid * DIM;
        float acc = 0.f;
        #pragma unroll 8
        for (int k = 0; k < DIM; k++) acc = fmaf(__ldg(wr + k), ps[k], acc);
        float y = (acc - mean[tid]) * (gamma[tid] * rsqrtf(var[tid] + BN_EPS)) + beta[tid];
        ys[tid] = fmaxf(y, 0.f);
    }
    __syncthreads();

    #pragma unroll
    for (int rep = 0; rep < 2; rep++) {
        const int o = rep * 512 + tid;
        if (o < OUTC) {
            const float* wr = w2 + o * HID;
            float acc = b2[o];
            #pragma unroll 5
            for (int h = 0; h < HID; h++) acc = fmaf(__ldg(wr + h), ys[h], acc);
            g_w[b * OUTC + o] = acc;
        }
    }

    if (tid == 0) g_count[b] = 0;                         // reset for next replay
}

// ---------------------------------------------------------------------------
// Kernel 2: depthwise 3-tap conv, pad=1, + bias. (identical to best R3 conv)
// grid=(8, DIM, BATCH), block=256, 2 float4s/thread, halo via warp shuffle,
// reversed traversal, __stcs stores.
// ---------------------------------------------------------------------------
__global__ void conv_kernel(const float* __restrict__ x,
                            const float* __restrict__ bias,
                            float* __restrict__ out) {
    const int b = (BATCH - 1) - blockIdx.z;
    const int c = (DIM - 1) - blockIdx.y;
    const int chunk = (int)(gridDim.x - 1) - blockIdx.x;     // 0..7
    const int tid = threadIdx.x;
    const int lane = tid & 31;
    const size_t rowoff = ((size_t)b * DIM + c) * SEQ;

    const float w0  = g_w[b * OUTC + c * KK + 0];
    const float w1v = g_w[b * OUTC + c * KK + 1];
    const float w2v = g_w[b * OUTC + c * KK + 2];
    const float bb  = __ldg(bias + c);

    const int p0 = chunk * 256 + tid;          // float4 idx, first half
    const int p1 = p0 + 2048;                  // second half
    const int t0 = p0 * 4;
    const int t1 = p1 * 4;

    const float4 xa = *(const float4*)(x + rowoff + t0);
    const float4 xb = *(const float4*)(x + rowoff + t1);

    float xla = __shfl_up_sync(FULLM, xa.w, 1);
    float xra = __shfl_down_sync(FULLM, xa.x, 1);
    float xlb = __shfl_up_sync(FULLM, xb.w, 1);
    float xrb = __shfl_down_sync(FULLM, xb.x, 1);

    if (lane == 0) {
        xla = (t0 == 0) ? 0.f : __ldg(x + rowoff + t0 - 1);
        xlb = __ldg(x + rowoff + t1 - 1);
    }
    if (lane == 31) {
        xra = __ldg(x + rowoff + t0 + 4);
        xrb = (t1 + 4 >= SEQ) ? 0.f : __ldg(x + rowoff + t1 + 4);
    }

    float4 oa, ob;
    oa.x = fmaf(w0, xla,  fmaf(w1v, xa.x, fmaf(w2v, xa.y, bb)));
    oa.y = fmaf(w0, xa.x, fmaf(w1v, xa.y, fmaf(w2v, xa.z, bb)));
    oa.z = fmaf(w0, xa.y, fmaf(w1v, xa.z, fmaf(w2v, xa.w, bb)));
    oa.w = fmaf(w0, xa.z, fmaf(w1v, xa.w, fmaf(w2v, xra,  bb)));

    ob.x = fmaf(w0, xlb,  fmaf(w1v, xb.x, fmaf(w2v, xb.y, bb)));
    ob.y = fmaf(w0, xb.x, fmaf(w1v, xb.y, fmaf(w2v, xb.z, bb)));
    ob.z = fmaf(w0, xb.y, fmaf(w1v, xb.z, fmaf(w2v, xb.w, bb)));
    ob.w = fmaf(w0, xb.z, fmaf(w1v, xb.w, fmaf(w2v, xrb,  bb)));

    __stcs((float4*)(out + rowoff + t0), oa);
    __stcs((float4*)(out + rowoff + t1), ob);
}

// ---------------------------------------------------------------------------
// Launch. Inputs (metadata order): x, w1, bn_gamma, bn_beta, bn_mean, bn_var,
// w2, b2, bias. Output: fp32 [8, 256, 16384].
// ---------------------------------------------------------------------------
extern "C" void kernel_launch(void* const* d_in, const int* in_sizes, int n_in,
                              void* d_out, int out_size) {
    const float* x     = (const float*)d_in[0];
    const float* w1    = (const float*)d_in[1];
    const float* gamma = (const float*)d_in[2];
    const float* beta  = (const float*)d_in[3];
    const float* mean  = (const float*)d_in[4];
    const float* var   = (const float*)d_in[5];
    const float* w2    = (const float*)d_in[6];
    const float* b2    = (const float*)d_in[7];
    const float* bias  = (const float*)d_in[8];
    float* out = (float*)d_out;

    dim3 pg(DIM, BATCH);
    pool_mlp_kernel<<<pg, 512>>>(x, w1, gamma, beta, mean, var, w2, b2);

    dim3 cg(8, DIM, BATCH);
    conv_kernel<<<cg, 256>>>(x, bias, out);
}